// round 2
// baseline (speedup 1.0000x reference)
#include <cuda_runtime.h>

// Problem constants
#define Bb  2
#define Ll  2048
#define Dd  2048
#define NHh 16
#define HDh 128

// Scratch (static device globals: allocation-free per harness rules)
// g_qkv viewed per batch as [3][NH][L][HD] (== row-major [L][3D], same memory)
__device__ float g_qkv[(size_t)Bb * Ll * 3 * Dd];   // ~100 MB
__device__ float g_attn[(size_t)Bb * Ll * Dd];      // ~33 MB

// ---------------------------------------------------------------------------
// SGEMM: C[M,N] = A[M,K] @ B[K,N] + bias[N]   (fp32, 128x128x16 tiles)
// ---------------------------------------------------------------------------
__global__ __launch_bounds__(256) void sgemm_bias_kernel(
    const float* __restrict__ A, const float* __restrict__ Bm,
    const float* __restrict__ bias, float* __restrict__ C,
    int M, int N, int K)
{
    __shared__ float As[16][128];   // transposed A tile: As[k][m]
    __shared__ float Bs[16][128];   // Bs[k][n]

    const int tid = threadIdx.x;
    const int tx  = tid & 15;
    const int ty  = tid >> 4;
    const int row0 = blockIdx.y * 128;
    const int col0 = blockIdx.x * 128;

    float acc[8][8];
#pragma unroll
    for (int i = 0; i < 8; i++)
#pragma unroll
        for (int j = 0; j < 8; j++) acc[i][j] = 0.f;

    for (int k0 = 0; k0 < K; k0 += 16) {
        // Load A tile (128 x 16) as float4, store transposed
#pragma unroll
        for (int l = 0; l < 2; l++) {
            int idx = tid + l * 256;        // 0..511
            int r   = idx >> 2;             // 0..127
            int c4  = idx & 3;              // 0..3
            float4 v = *(const float4*)(A + (size_t)(row0 + r) * K + k0 + c4 * 4);
            As[c4 * 4 + 0][r] = v.x;
            As[c4 * 4 + 1][r] = v.y;
            As[c4 * 4 + 2][r] = v.z;
            As[c4 * 4 + 3][r] = v.w;
        }
        // Load B tile (16 x 128) as float4
#pragma unroll
        for (int l = 0; l < 2; l++) {
            int idx = tid + l * 256;
            int r   = idx >> 5;             // 0..15
            int c4  = idx & 31;             // 0..31
            *(float4*)&Bs[r][c4 * 4] =
                *(const float4*)(Bm + (size_t)(k0 + r) * N + col0 + c4 * 4);
        }
        __syncthreads();

#pragma unroll
        for (int k = 0; k < 16; k++) {
            float a[8], b[8];
#pragma unroll
            for (int i = 0; i < 8; i++) a[i] = As[k][ty * 8 + i];
#pragma unroll
            for (int j = 0; j < 8; j++) b[j] = Bs[k][tx * 8 + j];
#pragma unroll
            for (int i = 0; i < 8; i++)
#pragma unroll
                for (int j = 0; j < 8; j++)
                    acc[i][j] = fmaf(a[i], b[j], acc[i][j]);
        }
        __syncthreads();
    }

    // Epilogue: + bias, vectorized store
#pragma unroll
    for (int i = 0; i < 8; i++) {
        int r = row0 + ty * 8 + i;
#pragma unroll
        for (int j4 = 0; j4 < 8; j4 += 4) {
            int c = col0 + tx * 8 + j4;
            float4 bv = *(const float4*)(bias + c);
            float4 o;
            o.x = acc[i][j4 + 0] + bv.x;
            o.y = acc[i][j4 + 1] + bv.y;
            o.z = acc[i][j4 + 2] + bv.z;
            o.w = acc[i][j4 + 3] + bv.w;
            *(float4*)(C + (size_t)r * N + c) = o;
        }
    }
}

// ---------------------------------------------------------------------------
// Flash attention (fp32, online softmax).
// Roles per reference einsum: S[i,j] = K[i,:]·Q[j,:], softmax over j,
// O[i,:] = sum_j P[i,j] V[j,:].   i tiles = 64 rows (blockIdx.x),
// j loop over full L in 64-col tiles.  Thread map: (ty,tx) in 16x16.
// S phase:  thread owns rows {ty+16r}, cols {tx+16c}  (4x4)
// PV phase: thread owns rows {ty+16r}, cols {tx*8..+7} (4x8 O accumulators)
// ---------------------------------------------------------------------------
#define KS_STR 132   // 128 + pad, 528B row stride (16B aligned, bank-spread)
#define PS_STR 68

#define ATTN_SMEM ((2 * 64 * KS_STR + 64 * PS_STR) * (int)sizeof(float))  // 84992 B

__global__ __launch_bounds__(256) void attn_kernel(
    const float* __restrict__ qkv, float* __restrict__ attn)
{
    const int h  = blockIdx.y;
    const int b  = blockIdx.z;
    const int i0 = blockIdx.x * 64;

    // per-batch flat layout: [3][NH][L][HD]
    const size_t head_stride = (size_t)Ll * HDh;
    const float* qb = qkv + ((size_t)b * 3 * NHh + 0 * NHh + h) * head_stride;
    const float* kb = qkv + ((size_t)b * 3 * NHh + 1 * NHh + h) * head_stride;
    const float* vb = qkv + ((size_t)b * 3 * NHh + 2 * NHh + h) * head_stride;

    extern __shared__ float smem[];
    float* Ks = smem;                    // [64][KS_STR]
    float* QV = smem + 64 * KS_STR;      // [64][KS_STR]  (Q tile, then reused for V)
    float* Ps = smem + 2 * 64 * KS_STR;  // [64][PS_STR]

    const int tid = threadIdx.x;
    const int tx  = tid & 15;
    const int ty  = tid >> 4;

    // Load K tile (rows i0..i0+63) once per block
#pragma unroll
    for (int l = 0; l < 8; l++) {
        int idx = tid + l * 256;         // 0..2047
        int r   = idx >> 5;
        int c4  = idx & 31;
        *(float4*)&Ks[r * KS_STR + c4 * 4] =
            *(const float4*)(kb + (size_t)(i0 + r) * HDh + c4 * 4);
    }

    float m[4], lsum[4], acc[4][8];
#pragma unroll
    for (int r = 0; r < 4; r++) {
        m[r] = -1e30f;
        lsum[r] = 0.f;
#pragma unroll
        for (int c = 0; c < 8; c++) acc[r][c] = 0.f;
    }
    const float rscale = 0.08838834764831845f;   // 1/sqrt(128)

    for (int j0 = 0; j0 < Ll; j0 += 64) {
        __syncthreads();   // previous PV done reading QV (V)
        // Load Q tile into QV
#pragma unroll
        for (int l = 0; l < 8; l++) {
            int idx = tid + l * 256;
            int r = idx >> 5, c4 = idx & 31;
            *(float4*)&QV[r * KS_STR + c4 * 4] =
                *(const float4*)(qb + (size_t)(j0 + r) * HDh + c4 * 4);
        }
        __syncthreads();

        // ---- S = K_i · Q_j  (4x4 per thread) ----
        float s[4][4];
#pragma unroll
        for (int r = 0; r < 4; r++)
#pragma unroll
            for (int c = 0; c < 4; c++) s[r][c] = 0.f;

#pragma unroll 4
        for (int d4 = 0; d4 < HDh; d4 += 4) {
            float4 ka[4], qv[4];
#pragma unroll
            for (int r = 0; r < 4; r++)
                ka[r] = *(const float4*)&Ks[(ty + 16 * r) * KS_STR + d4];
#pragma unroll
            for (int c = 0; c < 4; c++)
                qv[c] = *(const float4*)&QV[(tx + 16 * c) * KS_STR + d4];
#pragma unroll
            for (int r = 0; r < 4; r++)
#pragma unroll
                for (int c = 0; c < 4; c++) {
                    s[r][c] = fmaf(ka[r].x, qv[c].x, s[r][c]);
                    s[r][c] = fmaf(ka[r].y, qv[c].y, s[r][c]);
                    s[r][c] = fmaf(ka[r].z, qv[c].z, s[r][c]);
                    s[r][c] = fmaf(ka[r].w, qv[c].w, s[r][c]);
                }
        }

        // ---- online softmax: row stats shared across the 16 tx lanes ----
        float alpha[4];
#pragma unroll
        for (int r = 0; r < 4; r++) {
            float mx = -1e30f;
#pragma unroll
            for (int c = 0; c < 4; c++) {
                s[r][c] *= rscale;
                mx = fmaxf(mx, s[r][c]);
            }
#pragma unroll
            for (int o = 8; o >= 1; o >>= 1)
                mx = fmaxf(mx, __shfl_xor_sync(0xffffffffu, mx, o));
            float mn = fmaxf(m[r], mx);
            alpha[r] = __expf(m[r] - mn);
            m[r] = mn;
        }
#pragma unroll
        for (int r = 0; r < 4; r++) {
            float rs = 0.f;
#pragma unroll
            for (int c = 0; c < 4; c++) {
                float p = __expf(s[r][c] - m[r]);
                rs += p;
                Ps[(ty + 16 * r) * PS_STR + tx + 16 * c] = p;
            }
#pragma unroll
            for (int o = 8; o >= 1; o >>= 1)
                rs += __shfl_xor_sync(0xffffffffu, rs, o);
            lsum[r] = lsum[r] * alpha[r] + rs;
#pragma unroll
            for (int c = 0; c < 8; c++) acc[r][c] *= alpha[r];
        }
        __syncthreads();   // Ps complete; all reads of QV(Q) done

        // Load V tile into QV (overwrites Q)
#pragma unroll
        for (int l = 0; l < 8; l++) {
            int idx = tid + l * 256;
            int r = idx >> 5, c4 = idx & 31;
            *(float4*)&QV[r * KS_STR + c4 * 4] =
                *(const float4*)(vb + (size_t)(j0 + r) * HDh + c4 * 4);
        }
        __syncthreads();

        // ---- O += P @ V  (4 rows x 8 cols per thread) ----
#pragma unroll 4
        for (int j = 0; j < 64; j++) {
            float4 v0 = *(const float4*)&QV[j * KS_STR + tx * 8];
            float4 v1 = *(const float4*)&QV[j * KS_STR + tx * 8 + 4];
#pragma unroll
            for (int r = 0; r < 4; r++) {
                float p = Ps[(ty + 16 * r) * PS_STR + j];
                acc[r][0] = fmaf(p, v0.x, acc[r][0]);
                acc[r][1] = fmaf(p, v0.y, acc[r][1]);
                acc[r][2] = fmaf(p, v0.z, acc[r][2]);
                acc[r][3] = fmaf(p, v0.w, acc[r][3]);
                acc[r][4] = fmaf(p, v1.x, acc[r][4]);
                acc[r][5] = fmaf(p, v1.y, acc[r][5]);
                acc[r][6] = fmaf(p, v1.z, acc[r][6]);
                acc[r][7] = fmaf(p, v1.w, acc[r][7]);
            }
        }
    }

    // Write O: attn[b][i0+row][h*HD + col]   (transpose(0,2,1,3).reshape)
#pragma unroll
    for (int r = 0; r < 4; r++) {
        float inv = 1.f / lsum[r];
        int row = i0 + ty + 16 * r;
        float* dst = attn + ((size_t)b * Ll + row) * Dd + h * HDh + tx * 8;
        float4 o0, o1;
        o0.x = acc[r][0] * inv; o0.y = acc[r][1] * inv;
        o0.z = acc[r][2] * inv; o0.w = acc[r][3] * inv;
        o1.x = acc[r][4] * inv; o1.y = acc[r][5] * inv;
        o1.z = acc[r][6] * inv; o1.w = acc[r][7] * inv;
        *(float4*)(dst)     = o0;
        *(float4*)(dst + 4) = o1;
    }
}

// ---------------------------------------------------------------------------
extern "C" void kernel_launch(void* const* d_in, const int* in_sizes, int n_in,
                              void* d_out, int out_size)
{
    const float* x     = (const float*)d_in[0];
    const float* w_qkv = (const float*)d_in[1];
    const float* b_qkv = (const float*)d_in[2];
    const float* w_out = (const float*)d_in[3];
    const float* b_out = (const float*)d_in[4];
    float* out = (float*)d_out;

    float *qkv_ptr, *attn_ptr;
    cudaGetSymbolAddress((void**)&qkv_ptr,  g_qkv);
    cudaGetSymbolAddress((void**)&attn_ptr, g_attn);

    cudaFuncSetAttribute(attn_kernel,
                         cudaFuncAttributeMaxDynamicSharedMemorySize, ATTN_SMEM);

    // 1) QKV = X @ W_qkv + b_qkv     [4096 x 6144]
    sgemm_bias_kernel<<<dim3((3 * Dd) / 128, (Bb * Ll) / 128), 256>>>(
        x, w_qkv, b_qkv, qkv_ptr, Bb * Ll, 3 * Dd, Dd);

    // 2) attention (flash, fp32)
    attn_kernel<<<dim3(Ll / 64, NHh, Bb), 256, ATTN_SMEM>>>(qkv_ptr, attn_ptr);

    // 3) out = attn @ W_out + b_out  [4096 x 2048]
    sgemm_bias_kernel<<<dim3(Dd / 128, (Bb * Ll) / 128), 256>>>(
        attn_ptr, w_out, b_out, out, Bb * Ll, Dd, Dd);
}

// round 3
// speedup vs baseline: 1.5607x; 1.5607x over previous
#include <cuda_runtime.h>
#include <cuda_bf16.h>
#include <cstdint>

// Problem constants
#define Bb  2
#define Ll  2048
#define Dd  2048
#define NHh 16
#define HDh 128

// Scratch (static device globals: allocation-free per harness rules)
__device__ float g_qkv[(size_t)Bb * Ll * 3 * Dd];   // ~100 MB
__device__ float g_attn[(size_t)Bb * Ll * Dd];      // ~33 MB

// ===========================================================================
// bf16 hi/lo split GEMM on tensor cores.
// C[M,N] = A[M,K] @ B[K,N] + bias[N], fp32 in/out, fp32-equivalent accuracy:
//   A = Ahi + Alo, B = Bhi + Blo (bf16 each); C ≈ Ahi·Bhi + Ahi·Blo + Alo·Bhi
// Tiles: BM=128, BN=128, BK=32. 256 threads = 8 warps (4m × 2n),
// warp computes 32×64 via m16n8k16 mma (2 m-tiles × 8 n-tiles).
// ===========================================================================
#define BMt 128
#define BNt 128
#define BKt 32
#define ASTR 40     // bf16 elems per A smem row (32 + 8 pad) -> 80B, ldmatrix conflict-free
#define BSTR 136    // bf16 elems per B smem row (128 + 8 pad) -> 272B, conflict-free

#define A_TILE (BMt * ASTR)                    // 5120 bf16
#define B_TILE (BKt * BSTR)                    // 4352 bf16
#define STAGE_ELEMS (2 * A_TILE + 2 * B_TILE)  // 18944 bf16
#define GEMM_SMEM (2 * STAGE_ELEMS * (int)sizeof(__nv_bfloat16))  // 75776 B

__device__ __forceinline__ uint32_t smem_u32(const void* p) {
    return (uint32_t)__cvta_generic_to_shared(p);
}
__device__ __forceinline__ void ldsm_x4(uint32_t& r0, uint32_t& r1,
                                        uint32_t& r2, uint32_t& r3, uint32_t addr) {
    asm volatile("ldmatrix.sync.aligned.m8n8.x4.shared.b16 {%0,%1,%2,%3}, [%4];"
                 : "=r"(r0), "=r"(r1), "=r"(r2), "=r"(r3) : "r"(addr));
}
__device__ __forceinline__ void ldsm_x4_t(uint32_t& r0, uint32_t& r1,
                                          uint32_t& r2, uint32_t& r3, uint32_t addr) {
    asm volatile("ldmatrix.sync.aligned.m8n8.x4.trans.shared.b16 {%0,%1,%2,%3}, [%4];"
                 : "=r"(r0), "=r"(r1), "=r"(r2), "=r"(r3) : "r"(addr));
}
__device__ __forceinline__ void mma_bf16(float (&d)[4], const uint32_t (&a)[4],
                                         const uint32_t (&b)[2]) {
    asm volatile(
        "mma.sync.aligned.m16n8k16.row.col.f32.bf16.bf16.f32 "
        "{%0,%1,%2,%3},{%4,%5,%6,%7},{%8,%9},{%0,%1,%2,%3};"
        : "+f"(d[0]), "+f"(d[1]), "+f"(d[2]), "+f"(d[3])
        : "r"(a[0]), "r"(a[1]), "r"(a[2]), "r"(a[3]), "r"(b[0]), "r"(b[1]));
}

// split two fp32 into packed bf16x2 hi and lo
__device__ __forceinline__ void split2(float a, float b, uint32_t& hi, uint32_t& lo) {
    __nv_bfloat16 ha = __float2bfloat16_rn(a);
    __nv_bfloat16 hb = __float2bfloat16_rn(b);
    __nv_bfloat162 hp; hp.x = ha; hp.y = hb;
    hi = *(uint32_t*)&hp;
    float la = a - __bfloat162float(ha);
    float lb = b - __bfloat162float(hb);
    __nv_bfloat162 lp = __floats2bfloat162_rn(la, lb);
    lo = *(uint32_t*)&lp;
}

__global__ __launch_bounds__(256, 1) void gemm_bf16x3_kernel(
    const float* __restrict__ A, const float* __restrict__ Bm,
    const float* __restrict__ bias, float* __restrict__ C,
    int M, int N, int K)
{
    extern __shared__ __nv_bfloat16 sm[];
    const int tid  = threadIdx.x;
    const int lane = tid & 31;
    const int warp = tid >> 5;
    const int wm   = warp >> 1;   // 0..3: 32-row slab
    const int wn   = warp & 1;    // 0..1: 64-col slab
    const int row0 = blockIdx.y * BMt;
    const int col0 = blockIdx.x * BNt;

    float acc[2][8][4];
#pragma unroll
    for (int mi = 0; mi < 2; mi++)
#pragma unroll
        for (int ni = 0; ni < 8; ni++)
#pragma unroll
            for (int c = 0; c < 4; c++) acc[mi][ni][c] = 0.f;

    // gmem staging regs
    float4 ra[4], rb[4];
    const int ar  = tid >> 3;         // 0..31 base row group (4 rows per l implicit)
    const int ac4 = tid & 7;          // A col chunk
    const int br  = tid >> 5;         // B row (per l, +8 each)
    const int bc4 = tid & 31;         // B col chunk

    auto ldg_tiles = [&](int k0) {
#pragma unroll
        for (int l = 0; l < 4; l++) {
            int r = ar + l * 32;      // 0..127
            ra[l] = *(const float4*)(A + (size_t)(row0 + r) * K + k0 + ac4 * 4);
        }
#pragma unroll
        for (int l = 0; l < 4; l++) {
            int r = br + l * 8;       // 0..31
            rb[l] = *(const float4*)(Bm + (size_t)(k0 + r) * N + col0 + bc4 * 4);
        }
    };

    auto sts_tiles = [&](int s) {
        __nv_bfloat16* Ahi = sm + s * STAGE_ELEMS;
        __nv_bfloat16* Alo = Ahi + A_TILE;
        __nv_bfloat16* Bhi = Alo + A_TILE;
        __nv_bfloat16* Blo = Bhi + B_TILE;
#pragma unroll
        for (int l = 0; l < 4; l++) {
            int r = ar + l * 32;
            uint32_t h0, l0, h1, l1;
            split2(ra[l].x, ra[l].y, h0, l0);
            split2(ra[l].z, ra[l].w, h1, l1);
            uint2 hv = make_uint2(h0, h1), lv = make_uint2(l0, l1);
            *(uint2*)&Ahi[r * ASTR + ac4 * 4] = hv;
            *(uint2*)&Alo[r * ASTR + ac4 * 4] = lv;
        }
#pragma unroll
        for (int l = 0; l < 4; l++) {
            int r = br + l * 8;
            uint32_t h0, l0, h1, l1;
            split2(rb[l].x, rb[l].y, h0, l0);
            split2(rb[l].z, rb[l].w, h1, l1);
            uint2 hv = make_uint2(h0, h1), lv = make_uint2(l0, l1);
            *(uint2*)&Bhi[r * BSTR + bc4 * 4] = hv;
            *(uint2*)&Blo[r * BSTR + bc4 * 4] = lv;
        }
    };

    // ldmatrix per-lane offsets (element units)
    const int a_row = (lane & 15);
    const int a_col = (lane >> 4) << 3;
    const int b_row = (lane & 15);
    const int b_col = (lane >> 4) << 3;

    auto compute = [&](int s) {
        const __nv_bfloat16* Ahi = sm + s * STAGE_ELEMS;
        const __nv_bfloat16* Alo = Ahi + A_TILE;
        const __nv_bfloat16* Bhi = Alo + A_TILE;
        const __nv_bfloat16* Blo = Bhi + B_TILE;
#pragma unroll
        for (int kk = 0; kk < BKt; kk += 16) {
            uint32_t ah[2][4], al[2][4];
#pragma unroll
            for (int mi = 0; mi < 2; mi++) {
                int off = (wm * 32 + mi * 16 + a_row) * ASTR + kk + a_col;
                ldsm_x4(ah[mi][0], ah[mi][1], ah[mi][2], ah[mi][3], smem_u32(Ahi + off));
                ldsm_x4(al[mi][0], al[mi][1], al[mi][2], al[mi][3], smem_u32(Alo + off));
            }
            uint32_t bh[8][2], bl[8][2];
#pragma unroll
            for (int nb = 0; nb < 4; nb++) {
                int off = (kk + b_row) * BSTR + wn * 64 + nb * 16 + b_col;
                uint32_t t0, t1, t2, t3;
                ldsm_x4_t(t0, t1, t2, t3, smem_u32(Bhi + off));
                bh[2 * nb][0] = t0; bh[2 * nb][1] = t1;
                bh[2 * nb + 1][0] = t2; bh[2 * nb + 1][1] = t3;
                ldsm_x4_t(t0, t1, t2, t3, smem_u32(Blo + off));
                bl[2 * nb][0] = t0; bl[2 * nb][1] = t1;
                bl[2 * nb + 1][0] = t2; bl[2 * nb + 1][1] = t3;
            }
#pragma unroll
            for (int mi = 0; mi < 2; mi++)
#pragma unroll
                for (int ni = 0; ni < 8; ni++) {
                    mma_bf16(acc[mi][ni], ah[mi], bh[ni]);
                    mma_bf16(acc[mi][ni], ah[mi], bl[ni]);
                    mma_bf16(acc[mi][ni], al[mi], bh[ni]);
                }
        }
    };

    const int nK = K / BKt;
    ldg_tiles(0);
    sts_tiles(0);
    __syncthreads();

    for (int kb = 0; kb < nK; kb++) {
        int cur = kb & 1;
        if (kb + 1 < nK) ldg_tiles((kb + 1) * BKt);
        compute(cur);
        if (kb + 1 < nK) sts_tiles(1 - cur);
        __syncthreads();
    }

    // Epilogue: acc fragment layout -> C, + bias
    const int g  = lane >> 2;
    const int i2 = (lane & 3) * 2;
#pragma unroll
    for (int mi = 0; mi < 2; mi++) {
#pragma unroll
        for (int ni = 0; ni < 8; ni++) {
            int col = col0 + wn * 64 + ni * 8 + i2;
            float bx = bias[col], by = bias[col + 1];
            int r_top = row0 + wm * 32 + mi * 16 + g;
            float2 v0 = make_float2(acc[mi][ni][0] + bx, acc[mi][ni][1] + by);
            float2 v1 = make_float2(acc[mi][ni][2] + bx, acc[mi][ni][3] + by);
            *(float2*)(C + (size_t)r_top * N + col)       = v0;
            *(float2*)(C + (size_t)(r_top + 8) * N + col) = v1;
        }
    }
}

// ---------------------------------------------------------------------------
// Flash attention (fp32, online softmax) — unchanged from round 1.
// S[i,j] = K[i,:]·Q[j,:], softmax over j, O[i,:] = sum_j P[i,j] V[j,:].
// ---------------------------------------------------------------------------
#define KS_STR 132
#define PS_STR 68
#define ATTN_SMEM ((2 * 64 * KS_STR + 64 * PS_STR) * (int)sizeof(float))  // 84992 B

__global__ __launch_bounds__(256) void attn_kernel(
    const float* __restrict__ qkv, float* __restrict__ attn)
{
    const int h  = blockIdx.y;
    const int b  = blockIdx.z;
    const int i0 = blockIdx.x * 64;

    const size_t head_stride = (size_t)Ll * HDh;
    const float* qb = qkv + ((size_t)b * 3 * NHh + 0 * NHh + h) * head_stride;
    const float* kb = qkv + ((size_t)b * 3 * NHh + 1 * NHh + h) * head_stride;
    const float* vb = qkv + ((size_t)b * 3 * NHh + 2 * NHh + h) * head_stride;

    extern __shared__ float smem[];
    float* Ks = smem;
    float* QV = smem + 64 * KS_STR;
    float* Ps = smem + 2 * 64 * KS_STR;

    const int tid = threadIdx.x;
    const int tx  = tid & 15;
    const int ty  = tid >> 4;

#pragma unroll
    for (int l = 0; l < 8; l++) {
        int idx = tid + l * 256;
        int r   = idx >> 5;
        int c4  = idx & 31;
        *(float4*)&Ks[r * KS_STR + c4 * 4] =
            *(const float4*)(kb + (size_t)(i0 + r) * HDh + c4 * 4);
    }

    float m[4], lsum[4], acc[4][8];
#pragma unroll
    for (int r = 0; r < 4; r++) {
        m[r] = -1e30f;
        lsum[r] = 0.f;
#pragma unroll
        for (int c = 0; c < 8; c++) acc[r][c] = 0.f;
    }
    const float rscale = 0.08838834764831845f;   // 1/sqrt(128)

    for (int j0 = 0; j0 < Ll; j0 += 64) {
        __syncthreads();
#pragma unroll
        for (int l = 0; l < 8; l++) {
            int idx = tid + l * 256;
            int r = idx >> 5, c4 = idx & 31;
            *(float4*)&QV[r * KS_STR + c4 * 4] =
                *(const float4*)(qb + (size_t)(j0 + r) * HDh + c4 * 4);
        }
        __syncthreads();

        float s[4][4];
#pragma unroll
        for (int r = 0; r < 4; r++)
#pragma unroll
            for (int c = 0; c < 4; c++) s[r][c] = 0.f;

#pragma unroll 4
        for (int d4 = 0; d4 < HDh; d4 += 4) {
            float4 ka[4], qv[4];
#pragma unroll
            for (int r = 0; r < 4; r++)
                ka[r] = *(const float4*)&Ks[(ty + 16 * r) * KS_STR + d4];
#pragma unroll
            for (int c = 0; c < 4; c++)
                qv[c] = *(const float4*)&QV[(tx + 16 * c) * KS_STR + d4];
#pragma unroll
            for (int r = 0; r < 4; r++)
#pragma unroll
                for (int c = 0; c < 4; c++) {
                    s[r][c] = fmaf(ka[r].x, qv[c].x, s[r][c]);
                    s[r][c] = fmaf(ka[r].y, qv[c].y, s[r][c]);
                    s[r][c] = fmaf(ka[r].z, qv[c].z, s[r][c]);
                    s[r][c] = fmaf(ka[r].w, qv[c].w, s[r][c]);
                }
        }

        float alpha[4];
#pragma unroll
        for (int r = 0; r < 4; r++) {
            float mx = -1e30f;
#pragma unroll
            for (int c = 0; c < 4; c++) {
                s[r][c] *= rscale;
                mx = fmaxf(mx, s[r][c]);
            }
#pragma unroll
            for (int o = 8; o >= 1; o >>= 1)
                mx = fmaxf(mx, __shfl_xor_sync(0xffffffffu, mx, o));
            float mn = fmaxf(m[r], mx);
            alpha[r] = __expf(m[r] - mn);
            m[r] = mn;
        }
#pragma unroll
        for (int r = 0; r < 4; r++) {
            float rs = 0.f;
#pragma unroll
            for (int c = 0; c < 4; c++) {
                float p = __expf(s[r][c] - m[r]);
                rs += p;
                Ps[(ty + 16 * r) * PS_STR + tx + 16 * c] = p;
            }
#pragma unroll
            for (int o = 8; o >= 1; o >>= 1)
                rs += __shfl_xor_sync(0xffffffffu, rs, o);
            lsum[r] = lsum[r] * alpha[r] + rs;
#pragma unroll
            for (int c = 0; c < 8; c++) acc[r][c] *= alpha[r];
        }
        __syncthreads();

#pragma unroll
        for (int l = 0; l < 8; l++) {
            int idx = tid + l * 256;
            int r = idx >> 5, c4 = idx & 31;
            *(float4*)&QV[r * KS_STR + c4 * 4] =
                *(const float4*)(vb + (size_t)(j0 + r) * HDh + c4 * 4);
        }
        __syncthreads();

#pragma unroll 4
        for (int j = 0; j < 64; j++) {
            float4 v0 = *(const float4*)&QV[j * KS_STR + tx * 8];
            float4 v1 = *(const float4*)&QV[j * KS_STR + tx * 8 + 4];
#pragma unroll
            for (int r = 0; r < 4; r++) {
                float p = Ps[(ty + 16 * r) * PS_STR + j];
                acc[r][0] = fmaf(p, v0.x, acc[r][0]);
                acc[r][1] = fmaf(p, v0.y, acc[r][1]);
                acc[r][2] = fmaf(p, v0.z, acc[r][2]);
                acc[r][3] = fmaf(p, v0.w, acc[r][3]);
                acc[r][4] = fmaf(p, v1.x, acc[r][4]);
                acc[r][5] = fmaf(p, v1.y, acc[r][5]);
                acc[r][6] = fmaf(p, v1.z, acc[r][6]);
                acc[r][7] = fmaf(p, v1.w, acc[r][7]);
            }
        }
    }

#pragma unroll
    for (int r = 0; r < 4; r++) {
        float inv = 1.f / lsum[r];
        int row = i0 + ty + 16 * r;
        float* dst = attn + ((size_t)b * Ll + row) * Dd + h * HDh + tx * 8;
        float4 o0, o1;
        o0.x = acc[r][0] * inv; o0.y = acc[r][1] * inv;
        o0.z = acc[r][2] * inv; o0.w = acc[r][3] * inv;
        o1.x = acc[r][4] * inv; o1.y = acc[r][5] * inv;
        o1.z = acc[r][6] * inv; o1.w = acc[r][7] * inv;
        *(float4*)(dst)     = o0;
        *(float4*)(dst + 4) = o1;
    }
}

// ---------------------------------------------------------------------------
extern "C" void kernel_launch(void* const* d_in, const int* in_sizes, int n_in,
                              void* d_out, int out_size)
{
    const float* x     = (const float*)d_in[0];
    const float* w_qkv = (const float*)d_in[1];
    const float* b_qkv = (const float*)d_in[2];
    const float* w_out = (const float*)d_in[3];
    const float* b_out = (const float*)d_in[4];
    float* out = (float*)d_out;

    float *qkv_ptr, *attn_ptr;
    cudaGetSymbolAddress((void**)&qkv_ptr,  g_qkv);
    cudaGetSymbolAddress((void**)&attn_ptr, g_attn);

    cudaFuncSetAttribute(gemm_bf16x3_kernel,
                         cudaFuncAttributeMaxDynamicSharedMemorySize, GEMM_SMEM);
    cudaFuncSetAttribute(attn_kernel,
                         cudaFuncAttributeMaxDynamicSharedMemorySize, ATTN_SMEM);

    // 1) QKV = X @ W_qkv + b_qkv     [4096 x 6144]
    gemm_bf16x3_kernel<<<dim3((3 * Dd) / BNt, (Bb * Ll) / BMt), 256, GEMM_SMEM>>>(
        x, w_qkv, b_qkv, qkv_ptr, Bb * Ll, 3 * Dd, Dd);

    // 2) attention (flash, fp32)
    attn_kernel<<<dim3(Ll / 64, NHh, Bb), 256, ATTN_SMEM>>>(qkv_ptr, attn_ptr);

    // 3) out = attn @ W_out + b_out  [4096 x 2048]
    gemm_bf16x3_kernel<<<dim3(Dd / BNt, (Bb * Ll) / BMt), 256, GEMM_SMEM>>>(
        attn_ptr, w_out, b_out, out, Bb * Ll, Dd, Dd);
}

// round 4
// speedup vs baseline: 3.0652x; 1.9640x over previous
#include <cuda_runtime.h>
#include <cuda_bf16.h>
#include <cuda_fp16.h>
#include <cstdint>

// Problem constants
#define Bb  2
#define Ll  2048
#define Dd  2048
#define NHh 16
#define HDh 128

// Scratch (static device globals: allocation-free per harness rules)
__device__ float g_qkv[(size_t)Bb * Ll * 3 * Dd];   // ~100 MB
__device__ float g_attn[(size_t)Bb * Ll * Dd];      // ~33 MB

__device__ __forceinline__ uint32_t smem_u32(const void* p) {
    return (uint32_t)__cvta_generic_to_shared(p);
}
__device__ __forceinline__ void ldsm_x4(uint32_t& r0, uint32_t& r1,
                                        uint32_t& r2, uint32_t& r3, uint32_t addr) {
    asm volatile("ldmatrix.sync.aligned.m8n8.x4.shared.b16 {%0,%1,%2,%3}, [%4];"
                 : "=r"(r0), "=r"(r1), "=r"(r2), "=r"(r3) : "r"(addr));
}
__device__ __forceinline__ void ldsm_x4_t(uint32_t& r0, uint32_t& r1,
                                          uint32_t& r2, uint32_t& r3, uint32_t addr) {
    asm volatile("ldmatrix.sync.aligned.m8n8.x4.trans.shared.b16 {%0,%1,%2,%3}, [%4];"
                 : "=r"(r0), "=r"(r1), "=r"(r2), "=r"(r3) : "r"(addr));
}
__device__ __forceinline__ void mma_bf16(float (&d)[4], const uint32_t (&a)[4],
                                         const uint32_t b0, const uint32_t b1) {
    asm volatile(
        "mma.sync.aligned.m16n8k16.row.col.f32.bf16.bf16.f32 "
        "{%0,%1,%2,%3},{%4,%5,%6,%7},{%8,%9},{%0,%1,%2,%3};"
        : "+f"(d[0]), "+f"(d[1]), "+f"(d[2]), "+f"(d[3])
        : "r"(a[0]), "r"(a[1]), "r"(a[2]), "r"(a[3]), "r"(b0), "r"(b1));
}
__device__ __forceinline__ void mma_fp16(float (&d)[4], const uint32_t (&a)[4],
                                         const uint32_t b0, const uint32_t b1) {
    asm volatile(
        "mma.sync.aligned.m16n8k16.row.col.f32.f16.f16.f32 "
        "{%0,%1,%2,%3},{%4,%5,%6,%7},{%8,%9},{%0,%1,%2,%3};"
        : "+f"(d[0]), "+f"(d[1]), "+f"(d[2]), "+f"(d[3])
        : "r"(a[0]), "r"(a[1]), "r"(a[2]), "r"(a[3]), "r"(b0), "r"(b1));
}

// ===========================================================================
// bf16 hi/lo split GEMM on tensor cores (unchanged from round 2).
// ===========================================================================
#define BMt 128
#define BNt 128
#define BKt 32
#define ASTR 40
#define BSTR 136
#define A_TILE (BMt * ASTR)
#define B_TILE (BKt * BSTR)
#define STAGE_ELEMS (2 * A_TILE + 2 * B_TILE)
#define GEMM_SMEM (2 * STAGE_ELEMS * (int)sizeof(__nv_bfloat16))  // 75776 B

__device__ __forceinline__ void split2(float a, float b, uint32_t& hi, uint32_t& lo) {
    __nv_bfloat16 ha = __float2bfloat16_rn(a);
    __nv_bfloat16 hb = __float2bfloat16_rn(b);
    __nv_bfloat162 hp; hp.x = ha; hp.y = hb;
    hi = *(uint32_t*)&hp;
    float la = a - __bfloat162float(ha);
    float lb = b - __bfloat162float(hb);
    __nv_bfloat162 lp = __floats2bfloat162_rn(la, lb);
    lo = *(uint32_t*)&lp;
}

__global__ __launch_bounds__(256, 1) void gemm_bf16x3_kernel(
    const float* __restrict__ A, const float* __restrict__ Bm,
    const float* __restrict__ bias, float* __restrict__ C,
    int M, int N, int K)
{
    extern __shared__ __nv_bfloat16 sm[];
    const int tid  = threadIdx.x;
    const int lane = tid & 31;
    const int warp = tid >> 5;
    const int wm   = warp >> 1;
    const int wn   = warp & 1;
    const int row0 = blockIdx.y * BMt;
    const int col0 = blockIdx.x * BNt;

    float acc[2][8][4];
#pragma unroll
    for (int mi = 0; mi < 2; mi++)
#pragma unroll
        for (int ni = 0; ni < 8; ni++)
#pragma unroll
            for (int c = 0; c < 4; c++) acc[mi][ni][c] = 0.f;

    float4 ra[4], rb[4];
    const int ar  = tid >> 3;
    const int ac4 = tid & 7;
    const int br  = tid >> 5;
    const int bc4 = tid & 31;

    auto ldg_tiles = [&](int k0) {
#pragma unroll
        for (int l = 0; l < 4; l++) {
            int r = ar + l * 32;
            ra[l] = *(const float4*)(A + (size_t)(row0 + r) * K + k0 + ac4 * 4);
        }
#pragma unroll
        for (int l = 0; l < 4; l++) {
            int r = br + l * 8;
            rb[l] = *(const float4*)(Bm + (size_t)(k0 + r) * N + col0 + bc4 * 4);
        }
    };

    auto sts_tiles = [&](int s) {
        __nv_bfloat16* Ahi = sm + s * STAGE_ELEMS;
        __nv_bfloat16* Alo = Ahi + A_TILE;
        __nv_bfloat16* Bhi = Alo + A_TILE;
        __nv_bfloat16* Blo = Bhi + B_TILE;
#pragma unroll
        for (int l = 0; l < 4; l++) {
            int r = ar + l * 32;
            uint32_t h0, l0, h1, l1;
            split2(ra[l].x, ra[l].y, h0, l0);
            split2(ra[l].z, ra[l].w, h1, l1);
            *(uint2*)&Ahi[r * ASTR + ac4 * 4] = make_uint2(h0, h1);
            *(uint2*)&Alo[r * ASTR + ac4 * 4] = make_uint2(l0, l1);
        }
#pragma unroll
        for (int l = 0; l < 4; l++) {
            int r = br + l * 8;
            uint32_t h0, l0, h1, l1;
            split2(rb[l].x, rb[l].y, h0, l0);
            split2(rb[l].z, rb[l].w, h1, l1);
            *(uint2*)&Bhi[r * BSTR + bc4 * 4] = make_uint2(h0, h1);
            *(uint2*)&Blo[r * BSTR + bc4 * 4] = make_uint2(l0, l1);
        }
    };

    const int a_row = (lane & 15);
    const int a_col = (lane >> 4) << 3;

    auto compute = [&](int s) {
        const __nv_bfloat16* Ahi = sm + s * STAGE_ELEMS;
        const __nv_bfloat16* Alo = Ahi + A_TILE;
        const __nv_bfloat16* Bhi = Alo + A_TILE;
        const __nv_bfloat16* Blo = Bhi + B_TILE;
#pragma unroll
        for (int kk = 0; kk < BKt; kk += 16) {
            uint32_t ah[2][4], al[2][4];
#pragma unroll
            for (int mi = 0; mi < 2; mi++) {
                int off = (wm * 32 + mi * 16 + a_row) * ASTR + kk + a_col;
                ldsm_x4(ah[mi][0], ah[mi][1], ah[mi][2], ah[mi][3], smem_u32(Ahi + off));
                ldsm_x4(al[mi][0], al[mi][1], al[mi][2], al[mi][3], smem_u32(Alo + off));
            }
            uint32_t bh[8][2], bl[8][2];
#pragma unroll
            for (int nb = 0; nb < 4; nb++) {
                int off = (kk + a_row) * BSTR + wn * 64 + nb * 16 + a_col;
                uint32_t t0, t1, t2, t3;
                ldsm_x4_t(t0, t1, t2, t3, smem_u32(Bhi + off));
                bh[2 * nb][0] = t0; bh[2 * nb][1] = t1;
                bh[2 * nb + 1][0] = t2; bh[2 * nb + 1][1] = t3;
                ldsm_x4_t(t0, t1, t2, t3, smem_u32(Blo + off));
                bl[2 * nb][0] = t0; bl[2 * nb][1] = t1;
                bl[2 * nb + 1][0] = t2; bl[2 * nb + 1][1] = t3;
            }
#pragma unroll
            for (int mi = 0; mi < 2; mi++)
#pragma unroll
                for (int ni = 0; ni < 8; ni++) {
                    mma_bf16(acc[mi][ni], ah[mi], bh[ni][0], bh[ni][1]);
                    mma_bf16(acc[mi][ni], ah[mi], bl[ni][0], bl[ni][1]);
                    mma_bf16(acc[mi][ni], al[mi], bh[ni][0], bh[ni][1]);
                }
        }
    };

    const int nK = K / BKt;
    ldg_tiles(0);
    sts_tiles(0);
    __syncthreads();

    for (int kb = 0; kb < nK; kb++) {
        int cur = kb & 1;
        if (kb + 1 < nK) ldg_tiles((kb + 1) * BKt);
        compute(cur);
        if (kb + 1 < nK) sts_tiles(1 - cur);
        __syncthreads();
    }

    const int g  = lane >> 2;
    const int i2 = (lane & 3) * 2;
#pragma unroll
    for (int mi = 0; mi < 2; mi++) {
#pragma unroll
        for (int ni = 0; ni < 8; ni++) {
            int col = col0 + wn * 64 + ni * 8 + i2;
            float bx = bias[col], by = bias[col + 1];
            int r_top = row0 + wm * 32 + mi * 16 + g;
            *(float2*)(C + (size_t)r_top * N + col) =
                make_float2(acc[mi][ni][0] + bx, acc[mi][ni][1] + by);
            *(float2*)(C + (size_t)(r_top + 8) * N + col) =
                make_float2(acc[mi][ni][2] + bx, acc[mi][ni][3] + by);
        }
    }
}

// ===========================================================================
// Flash attention, fp16 tensor-core MMA, fp32 accumulate + online softmax.
// S[i,j] = K_i·Q_j (A=K, B=Q via plain ldmatrix, both k-contiguous),
// softmax over j, O += P@V (A=P from in-register S fragments, B=V via
// ldmatrix.trans). CTA: 128 i-rows (K resident), j-loop in 64-wide tiles.
// 8 warps, each owns 16 i-rows. Q/V prefetched to regs during compute.
// ===========================================================================
#define QSTR 136   // fp16 elems per smem row (128 + 8 pad), 272B stride
#define KS_ELEMS (128 * QSTR)
#define QS_ELEMS (64 * QSTR)
#define ATTN_SMEM ((KS_ELEMS + 2 * QS_ELEMS) * (int)sizeof(__half))  // 69632 B

__device__ __forceinline__ uint2 f4_to_h4(float4 v) {
    __half2 a = __floats2half2_rn(v.x, v.y);
    __half2 b = __floats2half2_rn(v.z, v.w);
    return make_uint2(*(uint32_t*)&a, *(uint32_t*)&b);
}

__global__ __launch_bounds__(256, 1) void attn_mma_kernel(
    const float* __restrict__ qkv, float* __restrict__ attn)
{
    const int h  = blockIdx.y;
    const int b  = blockIdx.z;
    const int i0 = blockIdx.x * 128;

    const size_t head_stride = (size_t)Ll * HDh;
    const float* qb = qkv + ((size_t)b * 3 * NHh + 0 * NHh + h) * head_stride;
    const float* kb = qkv + ((size_t)b * 3 * NHh + 1 * NHh + h) * head_stride;
    const float* vb = qkv + ((size_t)b * 3 * NHh + 2 * NHh + h) * head_stride;

    extern __shared__ __half smh[];
    __half* Ks = smh;                       // [128][QSTR]
    __half* Qs = smh + KS_ELEMS;            // [64][QSTR]
    __half* Vs = smh + KS_ELEMS + QS_ELEMS; // [64][QSTR]

    const int tid  = threadIdx.x;
    const int lane = tid & 31;
    const int w    = tid >> 5;

    // ---- load K tile (128 x 128 fp32 -> fp16 smem) ----
#pragma unroll
    for (int l = 0; l < 16; l++) {
        int idx = tid + l * 256;          // 0..4095 float4s
        int r   = idx >> 5;
        int c4  = idx & 31;
        float4 v = *(const float4*)(kb + (size_t)(i0 + r) * HDh + c4 * 4);
        *(uint2*)&Ks[r * QSTR + c4 * 4] = f4_to_h4(v);
    }

    // softmax state (2 rows per thread: g = lane>>2 and g+8)
    float m0 = -1e30f, m1 = -1e30f, l0 = 0.f, l1 = 0.f;
    float of[16][4];
#pragma unroll
    for (int f = 0; f < 16; f++)
#pragma unroll
        for (int c = 0; c < 4; c++) of[f][c] = 0.f;

    const float rscale = 0.08838834764831845f;   // 1/sqrt(128)

    // gmem staging regs for Q/V prefetch (8 float4 each)
    float4 rq[8], rv[8];
    const int sr  = tid >> 2;   // 0..63  (row)
    const int sc  = tid & 3;    // chunk base

    auto ldg_qv = [&](int j0) {
#pragma unroll
        for (int l = 0; l < 8; l++) {
            int c4 = sc + l * 4;    // 0..31
            rq[l] = *(const float4*)(qb + (size_t)(j0 + sr) * HDh + c4 * 4);
            rv[l] = *(const float4*)(vb + (size_t)(j0 + sr) * HDh + c4 * 4);
        }
    };
    auto sts_qv = [&]() {
#pragma unroll
        for (int l = 0; l < 8; l++) {
            int c4 = sc + l * 4;
            *(uint2*)&Qs[sr * QSTR + c4 * 4] = f4_to_h4(rq[l]);
            *(uint2*)&Vs[sr * QSTR + c4 * 4] = f4_to_h4(rv[l]);
        }
    };

    const int a_row = lane & 15;
    const int a_col = (lane >> 4) << 3;

    ldg_qv(0);
    sts_qv();
    __syncthreads();

    const int NT = Ll / 64;
    for (int jt = 0; jt < NT; jt++) {
        if (jt + 1 < NT) ldg_qv((jt + 1) * 64);

        // ---- S = K_i · Q_j : m16 (i) x n64 (j), k = 128 ----
        float sf[8][4];
#pragma unroll
        for (int nf = 0; nf < 8; nf++)
#pragma unroll
            for (int c = 0; c < 4; c++) sf[nf][c] = 0.f;

#pragma unroll
        for (int kk = 0; kk < 8; kk++) {
            int k16 = kk * 16;
            uint32_t af[4];
            ldsm_x4(af[0], af[1], af[2], af[3],
                    smem_u32(Ks + (w * 16 + a_row) * QSTR + k16 + a_col));
#pragma unroll
            for (int q = 0; q < 4; q++) {
                uint32_t t0, t1, t2, t3;
                ldsm_x4(t0, t1, t2, t3,
                        smem_u32(Qs + (q * 16 + a_row) * QSTR + k16 + a_col));
                // non-trans pairing: first n8 = (t0,t2), second n8 = (t1,t3)
                mma_fp16(sf[2 * q],     af, t0, t2);
                mma_fp16(sf[2 * q + 1], af, t1, t3);
            }
        }

        // ---- online softmax over this 64-col slab ----
#pragma unroll
        for (int nf = 0; nf < 8; nf++)
#pragma unroll
            for (int c = 0; c < 4; c++) sf[nf][c] *= rscale;

        float mx0 = -1e30f, mx1 = -1e30f;
#pragma unroll
        for (int nf = 0; nf < 8; nf++) {
            mx0 = fmaxf(mx0, fmaxf(sf[nf][0], sf[nf][1]));
            mx1 = fmaxf(mx1, fmaxf(sf[nf][2], sf[nf][3]));
        }
        mx0 = fmaxf(mx0, __shfl_xor_sync(0xffffffffu, mx0, 1));
        mx0 = fmaxf(mx0, __shfl_xor_sync(0xffffffffu, mx0, 2));
        mx1 = fmaxf(mx1, __shfl_xor_sync(0xffffffffu, mx1, 1));
        mx1 = fmaxf(mx1, __shfl_xor_sync(0xffffffffu, mx1, 2));

        float mn0 = fmaxf(m0, mx0), mn1 = fmaxf(m1, mx1);
        float alpha0 = __expf(m0 - mn0), alpha1 = __expf(m1 - mn1);
        m0 = mn0; m1 = mn1;

        float rs0 = 0.f, rs1 = 0.f;
#pragma unroll
        for (int nf = 0; nf < 8; nf++) {
            sf[nf][0] = __expf(sf[nf][0] - m0);
            sf[nf][1] = __expf(sf[nf][1] - m0);
            sf[nf][2] = __expf(sf[nf][2] - m1);
            sf[nf][3] = __expf(sf[nf][3] - m1);
            rs0 += sf[nf][0] + sf[nf][1];
            rs1 += sf[nf][2] + sf[nf][3];
        }
        rs0 += __shfl_xor_sync(0xffffffffu, rs0, 1);
        rs0 += __shfl_xor_sync(0xffffffffu, rs0, 2);
        rs1 += __shfl_xor_sync(0xffffffffu, rs1, 1);
        rs1 += __shfl_xor_sync(0xffffffffu, rs1, 2);
        l0 = l0 * alpha0 + rs0;
        l1 = l1 * alpha1 + rs1;

#pragma unroll
        for (int f = 0; f < 16; f++) {
            of[f][0] *= alpha0; of[f][1] *= alpha0;
            of[f][2] *= alpha1; of[f][3] *= alpha1;
        }

        // ---- pack P into A fragments (register-only, no smem) ----
        uint32_t pf[4][4];
#pragma unroll
        for (int kc = 0; kc < 4; kc++) {
            __half2 h;
            h = __floats2half2_rn(sf[2 * kc][0], sf[2 * kc][1]);     pf[kc][0] = *(uint32_t*)&h;
            h = __floats2half2_rn(sf[2 * kc][2], sf[2 * kc][3]);     pf[kc][1] = *(uint32_t*)&h;
            h = __floats2half2_rn(sf[2 * kc + 1][0], sf[2 * kc + 1][1]); pf[kc][2] = *(uint32_t*)&h;
            h = __floats2half2_rn(sf[2 * kc + 1][2], sf[2 * kc + 1][3]); pf[kc][3] = *(uint32_t*)&h;
        }

        // ---- O += P @ V : m16 (i) x n128 (d), k = 64 (j) ----
#pragma unroll
        for (int kc = 0; kc < 4; kc++) {
#pragma unroll
            for (int nb = 0; nb < 8; nb++) {
                uint32_t t0, t1, t2, t3;
                ldsm_x4_t(t0, t1, t2, t3,
                          smem_u32(Vs + (kc * 16 + a_row) * QSTR + nb * 16 + a_col));
                mma_fp16(of[2 * nb],     pf[kc], t0, t1);
                mma_fp16(of[2 * nb + 1], pf[kc], t2, t3);
            }
        }

        __syncthreads();   // all reads of Qs/Vs done
        if (jt + 1 < NT) {
            sts_qv();
            __syncthreads();
        }
    }

    // ---- write O (normalized) ----
    float inv0 = 1.f / l0, inv1 = 1.f / l1;
    int row_g = i0 + w * 16 + (lane >> 2);
    float* base = attn + ((size_t)b * Ll + row_g) * Dd + h * HDh + (lane & 3) * 2;
#pragma unroll
    for (int nf = 0; nf < 16; nf++) {
        *(float2*)(base + nf * 8) =
            make_float2(of[nf][0] * inv0, of[nf][1] * inv0);
        *(float2*)(base + 8 * Dd + nf * 8) =
            make_float2(of[nf][2] * inv1, of[nf][3] * inv1);
    }
}

// ---------------------------------------------------------------------------
extern "C" void kernel_launch(void* const* d_in, const int* in_sizes, int n_in,
                              void* d_out, int out_size)
{
    const float* x     = (const float*)d_in[0];
    const float* w_qkv = (const float*)d_in[1];
    const float* b_qkv = (const float*)d_in[2];
    const float* w_out = (const float*)d_in[3];
    const float* b_out = (const float*)d_in[4];
    float* out = (float*)d_out;

    float *qkv_ptr, *attn_ptr;
    cudaGetSymbolAddress((void**)&qkv_ptr,  g_qkv);
    cudaGetSymbolAddress((void**)&attn_ptr, g_attn);

    cudaFuncSetAttribute(gemm_bf16x3_kernel,
                         cudaFuncAttributeMaxDynamicSharedMemorySize, GEMM_SMEM);
    cudaFuncSetAttribute(attn_mma_kernel,
                         cudaFuncAttributeMaxDynamicSharedMemorySize, ATTN_SMEM);

    // 1) QKV = X @ W_qkv + b_qkv     [4096 x 6144]
    gemm_bf16x3_kernel<<<dim3((3 * Dd) / BNt, (Bb * Ll) / BMt), 256, GEMM_SMEM>>>(
        x, w_qkv, b_qkv, qkv_ptr, Bb * Ll, 3 * Dd, Dd);

    // 2) attention (flash, fp16 tensor cores)
    attn_mma_kernel<<<dim3(Ll / 128, NHh, Bb), 256, ATTN_SMEM>>>(qkv_ptr, attn_ptr);

    // 3) out = attn @ W_out + b_out  [4096 x 2048]
    gemm_bf16x3_kernel<<<dim3(Dd / BNt, (Bb * Ll) / BMt), 256, GEMM_SMEM>>>(
        attn_ptr, w_out, b_out, out, Bb * Ll, Dd, Dd);
}

// round 7
// speedup vs baseline: 6.6101x; 2.1565x over previous
#include <cuda_runtime.h>
#include <cuda_fp16.h>
#include <cstdint>

// Problem constants
#define Bb  2
#define Ll  2048
#define Dd  2048
#define NHh 16
#define HDh 128
#define Mtot (Bb * Ll)   // 4096

// Scratch (static device globals: allocation-free per harness rules)
__device__ __half g_qkvh[(size_t)Mtot * 3 * Dd];   // 50 MB (fp16 QKV)
__device__ __half g_xh  [(size_t)Mtot * Dd];       // 16 MB
__device__ __half g_wqt [(size_t)3 * Dd * Dd];     // 24 MB (W_qkv^T, K-major)
__device__ __half g_wot [(size_t)Dd * Dd];         //  8 MB (W_out^T, K-major)
__device__ __half g_oh  [(size_t)Mtot * Dd];       // 16 MB (attention O)

// ===========================================================================
// helpers
// ===========================================================================
__device__ __forceinline__ uint32_t smem_u32(const void* p) {
    return (uint32_t)__cvta_generic_to_shared(p);
}
__device__ __forceinline__ void ldsm_x4(uint32_t& r0, uint32_t& r1,
                                        uint32_t& r2, uint32_t& r3, uint32_t addr) {
    asm volatile("ldmatrix.sync.aligned.m8n8.x4.shared.b16 {%0,%1,%2,%3}, [%4];"
                 : "=r"(r0), "=r"(r1), "=r"(r2), "=r"(r3) : "r"(addr));
}
__device__ __forceinline__ void ldsm_x4_t(uint32_t& r0, uint32_t& r1,
                                          uint32_t& r2, uint32_t& r3, uint32_t addr) {
    asm volatile("ldmatrix.sync.aligned.m8n8.x4.trans.shared.b16 {%0,%1,%2,%3}, [%4];"
                 : "=r"(r0), "=r"(r1), "=r"(r2), "=r"(r3) : "r"(addr));
}
__device__ __forceinline__ void mma_fp16(float (&d)[4], const uint32_t (&a)[4],
                                         const uint32_t b0, const uint32_t b1) {
    asm volatile(
        "mma.sync.aligned.m16n8k16.row.col.f32.f16.f16.f32 "
        "{%0,%1,%2,%3},{%4,%5,%6,%7},{%8,%9},{%0,%1,%2,%3};"
        : "+f"(d[0]), "+f"(d[1]), "+f"(d[2]), "+f"(d[3])
        : "r"(a[0]), "r"(a[1]), "r"(a[2]), "r"(a[3]), "r"(b0), "r"(b1));
}
__device__ __forceinline__ void cp_async16(uint32_t d, const void* g) {
    asm volatile("cp.async.cg.shared.global [%0], [%1], 16;" :: "r"(d), "l"(g) : "memory");
}
__device__ __forceinline__ void cp_commit() {
    asm volatile("cp.async.commit_group;" ::: "memory");
}
template<int n> __device__ __forceinline__ void cp_wait() {
    asm volatile("cp.async.wait_group %0;" :: "n"(n) : "memory");
}
__device__ __forceinline__ uint32_t sw128(uint32_t bo) {   // Swizzle<3,4,3>
    return bo ^ ((bo >> 3) & 0x70);
}

// ===========================================================================
// prep kernels: fp32 -> fp16 convert (x), transpose+convert (weights)
// ===========================================================================
__global__ __launch_bounds__(256) void convert_x_kernel(
    const float* __restrict__ X, __half* __restrict__ Xh)
{
    size_t i = (size_t)blockIdx.x * 256 + threadIdx.x;   // float4 index
    float4 v = ((const float4*)X)[i];
    __half2 a = __floats2half2_rn(v.x, v.y);
    __half2 b = __floats2half2_rn(v.z, v.w);
    ((uint2*)Xh)[i] = make_uint2(*(uint32_t*)&a, *(uint32_t*)&b);
}

// W [K][N] fp32 -> T [N][K] fp16 (K-major)
__global__ __launch_bounds__(256) void transpose_cvt_kernel(
    const float* __restrict__ W, __half* __restrict__ T, int K, int N)
{
    __shared__ float t[32][33];
    int n0 = blockIdx.x * 32, k0 = blockIdx.y * 32;
    int c = threadIdx.x & 31, r8 = threadIdx.x >> 5;
#pragma unroll
    for (int i = 0; i < 4; i++) {
        int r = r8 + i * 8;
        t[r][c] = W[(size_t)(k0 + r) * N + n0 + c];
    }
    __syncthreads();
#pragma unroll
    for (int i = 0; i < 4; i++) {
        int r = r8 + i * 8;                      // local n index
        T[(size_t)(n0 + r) * K + k0 + c] = __float2half_rn(t[c][r]);
    }
}

// ===========================================================================
// fp16 GEMM (mma.sync): C[M,N] = A[M,K] @ B[N,K]^T + bias
// BM=256, BN=128, BK=64. 256 threads = 8 warps (4m x 2n), warp tile 64x64.
// 3-stage cp.async ring, SW128-swizzled smem, plain ldmatrix for A and B.
// OUT_HALF: write fp16 (QKV); else fp32 (final out).
// ===========================================================================
#define GBM 256
#define GBN 128
#define GBK 64
#define GA_BYTES (GBM * 128)               // 32768
#define GB_BYTES (GBN * 128)               // 16384
#define GSTAGE_B (GA_BYTES + GB_BYTES)     // 49152
#define GNST 3
#define GEMM_SMEM (GNST * GSTAGE_B)        // 147456

template<bool OUT_HALF>
__global__ __launch_bounds__(256, 1) void gemm_fp16_kernel(
    const __half* __restrict__ A, const __half* __restrict__ Bw,
    const float* __restrict__ bias, void* __restrict__ Cout, int N, int K)
{
    extern __shared__ __align__(1024) uint8_t smem[];
    const uint32_t sb = smem_u32(smem);
    const int tid = threadIdx.x, lane = tid & 31, warp = tid >> 5;
    const int wm = warp >> 1, wn = warp & 1;
    const int row0 = blockIdx.y * GBM, col0 = blockIdx.x * GBN;

    float acc[4][8][4];
#pragma unroll
    for (int mi = 0; mi < 4; mi++)
#pragma unroll
        for (int ni = 0; ni < 8; ni++)
#pragma unroll
            for (int c = 0; c < 4; c++) acc[mi][ni][c] = 0.f;

    auto load_stage = [&](int s, int kc) {
        const uint32_t st = sb + s * GSTAGE_B;
        const int k0 = kc * GBK;
#pragma unroll
        for (int i = 0; i < 8; i++) {          // A: 2048 16B chunks
            int idx = tid + i * 256;
            int r = idx >> 3, c = idx & 7;
            uint32_t bo = (uint32_t)(r * 128 + c * 16);
            cp_async16(st + sw128(bo), A + (size_t)(row0 + r) * K + k0 + c * 8);
        }
#pragma unroll
        for (int i = 0; i < 4; i++) {          // B: 1024 16B chunks
            int idx = tid + i * 256;
            int r = idx >> 3, c = idx & 7;
            uint32_t bo = (uint32_t)(r * 128 + c * 16);
            cp_async16(st + GA_BYTES + sw128(bo),
                       Bw + (size_t)(col0 + r) * K + k0 + c * 8);
        }
    };

    const int lrow = lane & 15;
    const int lcol = (lane >> 4) * 16;         // byte offset of k-chunk

    auto compute = [&](int s) {
        const uint32_t stA = sb + s * GSTAGE_B;
        const uint32_t stB = stA + GA_BYTES;
#pragma unroll
        for (int k16 = 0; k16 < 4; k16++) {
            uint32_t a[4][4];
#pragma unroll
            for (int mi = 0; mi < 4; mi++) {
                uint32_t bo = (uint32_t)((wm * 64 + mi * 16 + lrow) * 128 + k16 * 32 + lcol);
                ldsm_x4(a[mi][0], a[mi][1], a[mi][2], a[mi][3], stA + sw128(bo));
            }
            uint32_t bf[8][2];
#pragma unroll
            for (int nb = 0; nb < 4; nb++) {
                uint32_t bo = (uint32_t)((wn * 64 + nb * 16 + lrow) * 128 + k16 * 32 + lcol);
                uint32_t t0, t1, t2, t3;
                ldsm_x4(t0, t1, t2, t3, stB + sw128(bo));
                bf[2 * nb][0] = t0; bf[2 * nb][1] = t2;      // n8 lo: k0-7,k8-15
                bf[2 * nb + 1][0] = t1; bf[2 * nb + 1][1] = t3;
            }
#pragma unroll
            for (int mi = 0; mi < 4; mi++)
#pragma unroll
                for (int ni = 0; ni < 8; ni++)
                    mma_fp16(acc[mi][ni], a[mi], bf[ni][0], bf[ni][1]);
        }
    };

    const int nKC = K / GBK;                   // 32
    load_stage(0, 0); cp_commit();
    load_stage(1, 1); cp_commit();

    for (int kc = 0; kc < nKC; kc++) {
        const int s = kc % GNST;
        if (kc + 2 < nKC) { load_stage((kc + 2) % GNST, kc + 2); cp_commit(); }
        const int later = (nKC - 1 - kc) < 2 ? (nKC - 1 - kc) : 2;
        if (later == 2)      cp_wait<2>();
        else if (later == 1) cp_wait<1>();
        else                 cp_wait<0>();
        __syncthreads();
        compute(s);
        __syncthreads();
    }

    // Epilogue
    const int g  = lane >> 2;
    const int i2 = (lane & 3) * 2;
#pragma unroll
    for (int mi = 0; mi < 4; mi++) {
#pragma unroll
        for (int ni = 0; ni < 8; ni++) {
            int col = col0 + wn * 64 + ni * 8 + i2;
            float bx = bias[col], by = bias[col + 1];
            int r_top = row0 + wm * 64 + mi * 16 + g;
            float v0 = acc[mi][ni][0] + bx, v1 = acc[mi][ni][1] + by;
            float v2 = acc[mi][ni][2] + bx, v3 = acc[mi][ni][3] + by;
            if (OUT_HALF) {
                __half* C = (__half*)Cout;
                __half2 p0 = __floats2half2_rn(v0, v1);
                __half2 p1 = __floats2half2_rn(v2, v3);
                *(__half2*)(C + (size_t)r_top * N + col)       = p0;
                *(__half2*)(C + (size_t)(r_top + 8) * N + col) = p1;
            } else {
                float* C = (float*)Cout;
                *(float2*)(C + (size_t)r_top * N + col)       = make_float2(v0, v1);
                *(float2*)(C + (size_t)(r_top + 8) * N + col) = make_float2(v2, v3);
            }
        }
    }
}

// ===========================================================================
// Flash attention, fp16 MMA (R3 structure; now fp16 input + fp16 output).
// S[i,j] = K_i·Q_j, softmax over j, O += P@V. CTA: 128 i-rows, 64-wide j tiles.
// ===========================================================================
#define QSTR 136   // fp16 elems per smem row (128 + 8 pad), 272B stride
#define KS_ELEMS (128 * QSTR)
#define QS_ELEMS (64 * QSTR)
#define ATTN_SMEM ((KS_ELEMS + 2 * QS_ELEMS) * (int)sizeof(__half))  // 69632 B

__global__ __launch_bounds__(256, 1) void attn_mma_kernel(
    const __half* __restrict__ qkv, __half* __restrict__ O)
{
    const int h  = blockIdx.y;
    const int b  = blockIdx.z;
    const int i0 = blockIdx.x * 128;

    const size_t head_stride = (size_t)Ll * HDh;
    const __half* qb = qkv + ((size_t)b * 3 * NHh + 0 * NHh + h) * head_stride;
    const __half* kb = qkv + ((size_t)b * 3 * NHh + 1 * NHh + h) * head_stride;
    const __half* vb = qkv + ((size_t)b * 3 * NHh + 2 * NHh + h) * head_stride;

    extern __shared__ __half smh[];
    __half* Ks = smh;
    __half* Qs = smh + KS_ELEMS;
    __half* Vs = smh + KS_ELEMS + QS_ELEMS;

    const int tid  = threadIdx.x;
    const int lane = tid & 31;
    const int w    = tid >> 5;

    // ---- K tile: 128 rows x 256B = 2048 16B chunks ----
#pragma unroll
    for (int l = 0; l < 8; l++) {
        int idx = tid + l * 256;
        int r = idx >> 4, c = idx & 15;
        *(uint4*)&Ks[r * QSTR + c * 8] =
            *(const uint4*)(kb + (size_t)(i0 + r) * HDh + c * 8);
    }

    float m0 = -1e30f, m1 = -1e30f, l0 = 0.f, l1 = 0.f;
    float of[16][4];
#pragma unroll
    for (int f = 0; f < 16; f++)
#pragma unroll
        for (int c = 0; c < 4; c++) of[f][c] = 0.f;

    const float rscale = 0.08838834764831845f;   // 1/sqrt(128)

    uint4 rq[4], rv[4];
    const int sr = tid >> 2;       // 0..63 row
    const int scb = tid & 3;       // chunk base

    auto ldg_qv = [&](int j0) {
#pragma unroll
        for (int l = 0; l < 4; l++) {
            int c = scb + l * 4;   // 0..15
            rq[l] = *(const uint4*)(qb + (size_t)(j0 + sr) * HDh + c * 8);
            rv[l] = *(const uint4*)(vb + (size_t)(j0 + sr) * HDh + c * 8);
        }
    };
    auto sts_qv = [&]() {
#pragma unroll
        for (int l = 0; l < 4; l++) {
            int c = scb + l * 4;
            *(uint4*)&Qs[sr * QSTR + c * 8] = rq[l];
            *(uint4*)&Vs[sr * QSTR + c * 8] = rv[l];
        }
    };

    const int a_row = lane & 15;
    const int a_col = (lane >> 4) << 3;

    ldg_qv(0);
    sts_qv();
    __syncthreads();

    const int NT = Ll / 64;
    for (int jt = 0; jt < NT; jt++) {
        if (jt + 1 < NT) ldg_qv((jt + 1) * 64);

        float sf[8][4];
#pragma unroll
        for (int nf = 0; nf < 8; nf++)
#pragma unroll
            for (int c = 0; c < 4; c++) sf[nf][c] = 0.f;

#pragma unroll
        for (int kk = 0; kk < 8; kk++) {
            int k16 = kk * 16;
            uint32_t af[4];
            ldsm_x4(af[0], af[1], af[2], af[3],
                    smem_u32(Ks + (w * 16 + a_row) * QSTR + k16 + a_col));
#pragma unroll
            for (int q = 0; q < 4; q++) {
                uint32_t t0, t1, t2, t3;
                ldsm_x4(t0, t1, t2, t3,
                        smem_u32(Qs + (q * 16 + a_row) * QSTR + k16 + a_col));
                mma_fp16(sf[2 * q],     af, t0, t2);
                mma_fp16(sf[2 * q + 1], af, t1, t3);
            }
        }

#pragma unroll
        for (int nf = 0; nf < 8; nf++)
#pragma unroll
            for (int c = 0; c < 4; c++) sf[nf][c] *= rscale;

        float mx0 = -1e30f, mx1 = -1e30f;
#pragma unroll
        for (int nf = 0; nf < 8; nf++) {
            mx0 = fmaxf(mx0, fmaxf(sf[nf][0], sf[nf][1]));
            mx1 = fmaxf(mx1, fmaxf(sf[nf][2], sf[nf][3]));
        }
        mx0 = fmaxf(mx0, __shfl_xor_sync(0xffffffffu, mx0, 1));
        mx0 = fmaxf(mx0, __shfl_xor_sync(0xffffffffu, mx0, 2));
        mx1 = fmaxf(mx1, __shfl_xor_sync(0xffffffffu, mx1, 1));
        mx1 = fmaxf(mx1, __shfl_xor_sync(0xffffffffu, mx1, 2));

        float mn0 = fmaxf(m0, mx0), mn1 = fmaxf(m1, mx1);
        float alpha0 = __expf(m0 - mn0), alpha1 = __expf(m1 - mn1);
        m0 = mn0; m1 = mn1;

        float rs0 = 0.f, rs1 = 0.f;
#pragma unroll
        for (int nf = 0; nf < 8; nf++) {
            sf[nf][0] = __expf(sf[nf][0] - m0);
            sf[nf][1] = __expf(sf[nf][1] - m0);
            sf[nf][2] = __expf(sf[nf][2] - m1);
            sf[nf][3] = __expf(sf[nf][3] - m1);
            rs0 += sf[nf][0] + sf[nf][1];
            rs1 += sf[nf][2] + sf[nf][3];
        }
        rs0 += __shfl_xor_sync(0xffffffffu, rs0, 1);
        rs0 += __shfl_xor_sync(0xffffffffu, rs0, 2);
        rs1 += __shfl_xor_sync(0xffffffffu, rs1, 1);
        rs1 += __shfl_xor_sync(0xffffffffu, rs1, 2);
        l0 = l0 * alpha0 + rs0;
        l1 = l1 * alpha1 + rs1;

#pragma unroll
        for (int f = 0; f < 16; f++) {
            of[f][0] *= alpha0; of[f][1] *= alpha0;
            of[f][2] *= alpha1; of[f][3] *= alpha1;
        }

        uint32_t pf[4][4];
#pragma unroll
        for (int kc = 0; kc < 4; kc++) {
            __half2 hh;
            hh = __floats2half2_rn(sf[2 * kc][0], sf[2 * kc][1]);         pf[kc][0] = *(uint32_t*)&hh;
            hh = __floats2half2_rn(sf[2 * kc][2], sf[2 * kc][3]);         pf[kc][1] = *(uint32_t*)&hh;
            hh = __floats2half2_rn(sf[2 * kc + 1][0], sf[2 * kc + 1][1]); pf[kc][2] = *(uint32_t*)&hh;
            hh = __floats2half2_rn(sf[2 * kc + 1][2], sf[2 * kc + 1][3]); pf[kc][3] = *(uint32_t*)&hh;
        }

#pragma unroll
        for (int kc = 0; kc < 4; kc++) {
#pragma unroll
            for (int nb = 0; nb < 8; nb++) {
                uint32_t t0, t1, t2, t3;
                ldsm_x4_t(t0, t1, t2, t3,
                          smem_u32(Vs + (kc * 16 + a_row) * QSTR + nb * 16 + a_col));
                mma_fp16(of[2 * nb],     pf[kc], t0, t1);
                mma_fp16(of[2 * nb + 1], pf[kc], t2, t3);
            }
        }

        __syncthreads();
        if (jt + 1 < NT) {
            sts_qv();
            __syncthreads();
        }
    }

    // ---- write O as fp16 (input of proj GEMM) ----
    float inv0 = 1.f / l0, inv1 = 1.f / l1;
    int row_g = i0 + w * 16 + (lane >> 2);
    __half* base = O + ((size_t)b * Ll + row_g) * Dd + h * HDh + (lane & 3) * 2;
#pragma unroll
    for (int nf = 0; nf < 16; nf++) {
        __half2 p0 = __floats2half2_rn(of[nf][0] * inv0, of[nf][1] * inv0);
        __half2 p1 = __floats2half2_rn(of[nf][2] * inv1, of[nf][3] * inv1);
        *(__half2*)(base + nf * 8)          = p0;
        *(__half2*)(base + 8 * Dd + nf * 8) = p1;
    }
}

// ---------------------------------------------------------------------------
extern "C" void kernel_launch(void* const* d_in, const int* in_sizes, int n_in,
                              void* d_out, int out_size)
{
    const float* x     = (const float*)d_in[0];
    const float* w_qkv = (const float*)d_in[1];
    const float* b_qkv = (const float*)d_in[2];
    const float* w_out = (const float*)d_in[3];
    const float* b_out = (const float*)d_in[4];
    float* out = (float*)d_out;

    __half *qkvh, *xh, *wqt, *wot, *oh;
    cudaGetSymbolAddress((void**)&qkvh, g_qkvh);
    cudaGetSymbolAddress((void**)&xh,   g_xh);
    cudaGetSymbolAddress((void**)&wqt,  g_wqt);
    cudaGetSymbolAddress((void**)&wot,  g_wot);
    cudaGetSymbolAddress((void**)&oh,   g_oh);

    cudaFuncSetAttribute(gemm_fp16_kernel<true>,
                         cudaFuncAttributeMaxDynamicSharedMemorySize, GEMM_SMEM);
    cudaFuncSetAttribute(gemm_fp16_kernel<false>,
                         cudaFuncAttributeMaxDynamicSharedMemorySize, GEMM_SMEM);
    cudaFuncSetAttribute(attn_mma_kernel,
                         cudaFuncAttributeMaxDynamicSharedMemorySize, ATTN_SMEM);

    // 0) prep: convert x to fp16; transpose+convert weights to K-major fp16
    convert_x_kernel<<<(Mtot * Dd / 4) / 256, 256>>>(x, xh);
    transpose_cvt_kernel<<<dim3(3 * Dd / 32, Dd / 32), 256>>>(w_qkv, wqt, Dd, 3 * Dd);
    transpose_cvt_kernel<<<dim3(Dd / 32, Dd / 32), 256>>>(w_out, wot, Dd, Dd);

    // 1) QKV = X @ W_qkv + b_qkv  -> fp16
    gemm_fp16_kernel<true><<<dim3(3 * Dd / GBN, Mtot / GBM), 256, GEMM_SMEM>>>(
        xh, wqt, b_qkv, qkvh, 3 * Dd, Dd);

    // 2) attention (flash, fp16 mma) -> fp16 O
    attn_mma_kernel<<<dim3(Ll / 128, NHh, Bb), 256, ATTN_SMEM>>>(qkvh, oh);

    // 3) out = O @ W_out + b_out  -> fp32
    gemm_fp16_kernel<false><<<dim3(Dd / GBN, Mtot / GBM), 256, GEMM_SMEM>>>(
        oh, wot, b_out, out, Dd, Dd);
}

// round 8
// speedup vs baseline: 7.2677x; 1.0995x over previous
#include <cuda_runtime.h>
#include <cuda_fp16.h>
#include <cstdint>

// Problem constants
#define Bb  2
#define Ll  2048
#define Dd  2048
#define NHh 16
#define HDh 128
#define Mtot (Bb * Ll)   // 4096

// Scratch (static device globals: allocation-free per harness rules)
__device__ __half g_qkvh[(size_t)Mtot * 3 * Dd];   // 50 MB (fp16 QKV)
__device__ __half g_xh  [(size_t)Mtot * Dd];       // 16 MB
__device__ __half g_wqt [(size_t)3 * Dd * Dd];     // 24 MB (W_qkv^T, K-major)
__device__ __half g_wot [(size_t)Dd * Dd];         //  8 MB (W_out^T, K-major)
__device__ __half g_oh  [(size_t)Mtot * Dd];       // 16 MB (attention O)

// ===========================================================================
// helpers
// ===========================================================================
__device__ __forceinline__ uint32_t smem_u32(const void* p) {
    return (uint32_t)__cvta_generic_to_shared(p);
}
__device__ __forceinline__ void ldsm_x4(uint32_t& r0, uint32_t& r1,
                                        uint32_t& r2, uint32_t& r3, uint32_t addr) {
    asm volatile("ldmatrix.sync.aligned.m8n8.x4.shared.b16 {%0,%1,%2,%3}, [%4];"
                 : "=r"(r0), "=r"(r1), "=r"(r2), "=r"(r3) : "r"(addr));
}
__device__ __forceinline__ void ldsm_x4_t(uint32_t& r0, uint32_t& r1,
                                          uint32_t& r2, uint32_t& r3, uint32_t addr) {
    asm volatile("ldmatrix.sync.aligned.m8n8.x4.trans.shared.b16 {%0,%1,%2,%3}, [%4];"
                 : "=r"(r0), "=r"(r1), "=r"(r2), "=r"(r3) : "r"(addr));
}
__device__ __forceinline__ void mma_fp16(float (&d)[4], const uint32_t (&a)[4],
                                         const uint32_t b0, const uint32_t b1) {
    asm volatile(
        "mma.sync.aligned.m16n8k16.row.col.f32.f16.f16.f32 "
        "{%0,%1,%2,%3},{%4,%5,%6,%7},{%8,%9},{%0,%1,%2,%3};"
        : "+f"(d[0]), "+f"(d[1]), "+f"(d[2]), "+f"(d[3])
        : "r"(a[0]), "r"(a[1]), "r"(a[2]), "r"(a[3]), "r"(b0), "r"(b1));
}
__device__ __forceinline__ void cp_async16(uint32_t d, const void* g) {
    asm volatile("cp.async.cg.shared.global [%0], [%1], 16;" :: "r"(d), "l"(g) : "memory");
}
__device__ __forceinline__ void cp_commit() {
    asm volatile("cp.async.commit_group;" ::: "memory");
}
template<int n> __device__ __forceinline__ void cp_wait() {
    asm volatile("cp.async.wait_group %0;" :: "n"(n) : "memory");
}
__device__ __forceinline__ uint32_t sw128(uint32_t bo) {   // Swizzle<3,4,3>
    return bo ^ ((bo >> 3) & 0x70);
}

// ===========================================================================
// prep kernels: fp32 -> fp16 convert (x), transpose+convert (weights)
// ===========================================================================
__global__ __launch_bounds__(256) void convert_x_kernel(
    const float* __restrict__ X, __half* __restrict__ Xh)
{
    size_t i = (size_t)blockIdx.x * 256 + threadIdx.x;   // float4 index
    float4 v = ((const float4*)X)[i];
    __half2 a = __floats2half2_rn(v.x, v.y);
    __half2 b = __floats2half2_rn(v.z, v.w);
    ((uint2*)Xh)[i] = make_uint2(*(uint32_t*)&a, *(uint32_t*)&b);
}

// W [K][N] fp32 -> T [N][K] fp16 (K-major)
__global__ __launch_bounds__(256) void transpose_cvt_kernel(
    const float* __restrict__ W, __half* __restrict__ T, int K, int N)
{
    __shared__ float t[32][33];
    int n0 = blockIdx.x * 32, k0 = blockIdx.y * 32;
    int c = threadIdx.x & 31, r8 = threadIdx.x >> 5;
#pragma unroll
    for (int i = 0; i < 4; i++) {
        int r = r8 + i * 8;
        t[r][c] = W[(size_t)(k0 + r) * N + n0 + c];
    }
    __syncthreads();
#pragma unroll
    for (int i = 0; i < 4; i++) {
        int r = r8 + i * 8;                      // local n index
        T[(size_t)(n0 + r) * K + k0 + c] = __float2half_rn(t[c][r]);
    }
}

// ===========================================================================
// fp16 GEMM (mma.sync): C[M,N] = A[M,K] @ B[N,K]^T + bias
// BM=128, BN=128, BK=64. 256 threads = 8 warps (4m x 2n), warp tile 32x64.
// 3-stage cp.async ring, SW128-swizzled smem, 2 CTAs/SM (latency cover).
// ===========================================================================
#define GBM 128
#define GBN 128
#define GBK 64
#define GA_BYTES (GBM * 128)               // 16384
#define GB_BYTES (GBN * 128)               // 16384
#define GSTAGE_B (GA_BYTES + GB_BYTES)     // 32768
#define GNST 3
#define GEMM_SMEM (GNST * GSTAGE_B)        // 98304

template<bool OUT_HALF>
__global__ __launch_bounds__(256, 2) void gemm_fp16_kernel(
    const __half* __restrict__ A, const __half* __restrict__ Bw,
    const float* __restrict__ bias, void* __restrict__ Cout, int N, int K)
{
    extern __shared__ __align__(1024) uint8_t smem[];
    const uint32_t sb = smem_u32(smem);
    const int tid = threadIdx.x, lane = tid & 31, warp = tid >> 5;
    const int wm = warp >> 1, wn = warp & 1;
    const int row0 = blockIdx.y * GBM, col0 = blockIdx.x * GBN;

    float acc[2][8][4];
#pragma unroll
    for (int mi = 0; mi < 2; mi++)
#pragma unroll
        for (int ni = 0; ni < 8; ni++)
#pragma unroll
            for (int c = 0; c < 4; c++) acc[mi][ni][c] = 0.f;

    auto load_stage = [&](int s, int kc) {
        const uint32_t st = sb + s * GSTAGE_B;
        const int k0 = kc * GBK;
#pragma unroll
        for (int i = 0; i < 4; i++) {          // A: 1024 16B chunks
            int idx = tid + i * 256;
            int r = idx >> 3, c = idx & 7;
            uint32_t bo = (uint32_t)(r * 128 + c * 16);
            cp_async16(st + sw128(bo), A + (size_t)(row0 + r) * K + k0 + c * 8);
        }
#pragma unroll
        for (int i = 0; i < 4; i++) {          // B: 1024 16B chunks
            int idx = tid + i * 256;
            int r = idx >> 3, c = idx & 7;
            uint32_t bo = (uint32_t)(r * 128 + c * 16);
            cp_async16(st + GA_BYTES + sw128(bo),
                       Bw + (size_t)(col0 + r) * K + k0 + c * 8);
        }
    };

    const int lrow = lane & 15;
    const int lcol = (lane >> 4) * 16;         // byte offset of k-chunk

    auto compute = [&](int s) {
        const uint32_t stA = sb + s * GSTAGE_B;
        const uint32_t stB = stA + GA_BYTES;
#pragma unroll
        for (int k16 = 0; k16 < 4; k16++) {
            uint32_t a[2][4];
#pragma unroll
            for (int mi = 0; mi < 2; mi++) {
                uint32_t bo = (uint32_t)((wm * 32 + mi * 16 + lrow) * 128 + k16 * 32 + lcol);
                ldsm_x4(a[mi][0], a[mi][1], a[mi][2], a[mi][3], stA + sw128(bo));
            }
            uint32_t bf[8][2];
#pragma unroll
            for (int nb = 0; nb < 4; nb++) {
                uint32_t bo = (uint32_t)((wn * 64 + nb * 16 + lrow) * 128 + k16 * 32 + lcol);
                uint32_t t0, t1, t2, t3;
                ldsm_x4(t0, t1, t2, t3, stB + sw128(bo));
                bf[2 * nb][0] = t0; bf[2 * nb][1] = t2;      // n8 lo: k0-7,k8-15
                bf[2 * nb + 1][0] = t1; bf[2 * nb + 1][1] = t3;
            }
#pragma unroll
            for (int mi = 0; mi < 2; mi++)
#pragma unroll
                for (int ni = 0; ni < 8; ni++)
                    mma_fp16(acc[mi][ni], a[mi], bf[ni][0], bf[ni][1]);
        }
    };

    const int nKC = K / GBK;                   // 32
    load_stage(0, 0); cp_commit();
    load_stage(1, 1); cp_commit();

    for (int kc = 0; kc < nKC; kc++) {
        const int s = kc % GNST;
        if (kc + 2 < nKC) { load_stage((kc + 2) % GNST, kc + 2); cp_commit(); }
        const int later = (nKC - 1 - kc) < 2 ? (nKC - 1 - kc) : 2;
        if (later == 2)      cp_wait<2>();
        else if (later == 1) cp_wait<1>();
        else                 cp_wait<0>();
        __syncthreads();
        compute(s);
        __syncthreads();
    }

    // Epilogue
    const int g  = lane >> 2;
    const int i2 = (lane & 3) * 2;
#pragma unroll
    for (int mi = 0; mi < 2; mi++) {
#pragma unroll
        for (int ni = 0; ni < 8; ni++) {
            int col = col0 + wn * 64 + ni * 8 + i2;
            float bx = bias[col], by = bias[col + 1];
            int r_top = row0 + wm * 32 + mi * 16 + g;
            float v0 = acc[mi][ni][0] + bx, v1 = acc[mi][ni][1] + by;
            float v2 = acc[mi][ni][2] + bx, v3 = acc[mi][ni][3] + by;
            if (OUT_HALF) {
                __half* C = (__half*)Cout;
                __half2 p0 = __floats2half2_rn(v0, v1);
                __half2 p1 = __floats2half2_rn(v2, v3);
                *(__half2*)(C + (size_t)r_top * N + col)       = p0;
                *(__half2*)(C + (size_t)(r_top + 8) * N + col) = p1;
            } else {
                float* C = (float*)Cout;
                *(float2*)(C + (size_t)r_top * N + col)       = make_float2(v0, v1);
                *(float2*)(C + (size_t)(r_top + 8) * N + col) = make_float2(v2, v3);
            }
        }
    }
}

// ===========================================================================
// Flash attention, fp16 MMA (unchanged from R6 — measured ~81% tensor eff).
// S[i,j] = K_i·Q_j, softmax over j, O += P@V. CTA: 128 i-rows, 64-wide j tiles.
// ===========================================================================
#define QSTR 136   // fp16 elems per smem row (128 + 8 pad), 272B stride
#define KS_ELEMS (128 * QSTR)
#define QS_ELEMS (64 * QSTR)
#define ATTN_SMEM ((KS_ELEMS + 2 * QS_ELEMS) * (int)sizeof(__half))  // 69632 B

__global__ __launch_bounds__(256, 1) void attn_mma_kernel(
    const __half* __restrict__ qkv, __half* __restrict__ O)
{
    const int h  = blockIdx.y;
    const int b  = blockIdx.z;
    const int i0 = blockIdx.x * 128;

    const size_t head_stride = (size_t)Ll * HDh;
    const __half* qb = qkv + ((size_t)b * 3 * NHh + 0 * NHh + h) * head_stride;
    const __half* kb = qkv + ((size_t)b * 3 * NHh + 1 * NHh + h) * head_stride;
    const __half* vb = qkv + ((size_t)b * 3 * NHh + 2 * NHh + h) * head_stride;

    extern __shared__ __half smh[];
    __half* Ks = smh;
    __half* Qs = smh + KS_ELEMS;
    __half* Vs = smh + KS_ELEMS + QS_ELEMS;

    const int tid  = threadIdx.x;
    const int lane = tid & 31;
    const int w    = tid >> 5;

    // ---- K tile: 128 rows x 256B = 2048 16B chunks ----
#pragma unroll
    for (int l = 0; l < 8; l++) {
        int idx = tid + l * 256;
        int r = idx >> 4, c = idx & 15;
        *(uint4*)&Ks[r * QSTR + c * 8] =
            *(const uint4*)(kb + (size_t)(i0 + r) * HDh + c * 8);
    }

    float m0 = -1e30f, m1 = -1e30f, l0 = 0.f, l1 = 0.f;
    float of[16][4];
#pragma unroll
    for (int f = 0; f < 16; f++)
#pragma unroll
        for (int c = 0; c < 4; c++) of[f][c] = 0.f;

    const float rscale = 0.08838834764831845f;   // 1/sqrt(128)

    uint4 rq[4], rv[4];
    const int sr = tid >> 2;       // 0..63 row
    const int scb = tid & 3;       // chunk base

    auto ldg_qv = [&](int j0) {
#pragma unroll
        for (int l = 0; l < 4; l++) {
            int c = scb + l * 4;   // 0..15
            rq[l] = *(const uint4*)(qb + (size_t)(j0 + sr) * HDh + c * 8);
            rv[l] = *(const uint4*)(vb + (size_t)(j0 + sr) * HDh + c * 8);
        }
    };
    auto sts_qv = [&]() {
#pragma unroll
        for (int l = 0; l < 4; l++) {
            int c = scb + l * 4;
            *(uint4*)&Qs[sr * QSTR + c * 8] = rq[l];
            *(uint4*)&Vs[sr * QSTR + c * 8] = rv[l];
        }
    };

    const int a_row = lane & 15;
    const int a_col = (lane >> 4) << 3;

    ldg_qv(0);
    sts_qv();
    __syncthreads();

    const int NT = Ll / 64;
    for (int jt = 0; jt < NT; jt++) {
        if (jt + 1 < NT) ldg_qv((jt + 1) * 64);

        float sf[8][4];
#pragma unroll
        for (int nf = 0; nf < 8; nf++)
#pragma unroll
            for (int c = 0; c < 4; c++) sf[nf][c] = 0.f;

#pragma unroll
        for (int kk = 0; kk < 8; kk++) {
            int k16 = kk * 16;
            uint32_t af[4];
            ldsm_x4(af[0], af[1], af[2], af[3],
                    smem_u32(Ks + (w * 16 + a_row) * QSTR + k16 + a_col));
#pragma unroll
            for (int q = 0; q < 4; q++) {
                uint32_t t0, t1, t2, t3;
                ldsm_x4(t0, t1, t2, t3,
                        smem_u32(Qs + (q * 16 + a_row) * QSTR + k16 + a_col));
                mma_fp16(sf[2 * q],     af, t0, t2);
                mma_fp16(sf[2 * q + 1], af, t1, t3);
            }
        }

#pragma unroll
        for (int nf = 0; nf < 8; nf++)
#pragma unroll
            for (int c = 0; c < 4; c++) sf[nf][c] *= rscale;

        float mx0 = -1e30f, mx1 = -1e30f;
#pragma unroll
        for (int nf = 0; nf < 8; nf++) {
            mx0 = fmaxf(mx0, fmaxf(sf[nf][0], sf[nf][1]));
            mx1 = fmaxf(mx1, fmaxf(sf[nf][2], sf[nf][3]));
        }
        mx0 = fmaxf(mx0, __shfl_xor_sync(0xffffffffu, mx0, 1));
        mx0 = fmaxf(mx0, __shfl_xor_sync(0xffffffffu, mx0, 2));
        mx1 = fmaxf(mx1, __shfl_xor_sync(0xffffffffu, mx1, 1));
        mx1 = fmaxf(mx1, __shfl_xor_sync(0xffffffffu, mx1, 2));

        float mn0 = fmaxf(m0, mx0), mn1 = fmaxf(m1, mx1);
        float alpha0 = __expf(m0 - mn0), alpha1 = __expf(m1 - mn1);
        m0 = mn0; m1 = mn1;

        float rs0 = 0.f, rs1 = 0.f;
#pragma unroll
        for (int nf = 0; nf < 8; nf++) {
            sf[nf][0] = __expf(sf[nf][0] - m0);
            sf[nf][1] = __expf(sf[nf][1] - m0);
            sf[nf][2] = __expf(sf[nf][2] - m1);
            sf[nf][3] = __expf(sf[nf][3] - m1);
            rs0 += sf[nf][0] + sf[nf][1];
            rs1 += sf[nf][2] + sf[nf][3];
        }
        rs0 += __shfl_xor_sync(0xffffffffu, rs0, 1);
        rs0 += __shfl_xor_sync(0xffffffffu, rs0, 2);
        rs1 += __shfl_xor_sync(0xffffffffu, rs1, 1);
        rs1 += __shfl_xor_sync(0xffffffffu, rs1, 2);
        l0 = l0 * alpha0 + rs0;
        l1 = l1 * alpha1 + rs1;

#pragma unroll
        for (int f = 0; f < 16; f++) {
            of[f][0] *= alpha0; of[f][1] *= alpha0;
            of[f][2] *= alpha1; of[f][3] *= alpha1;
        }

        uint32_t pf[4][4];
#pragma unroll
        for (int kc = 0; kc < 4; kc++) {
            __half2 hh;
            hh = __floats2half2_rn(sf[2 * kc][0], sf[2 * kc][1]);         pf[kc][0] = *(uint32_t*)&hh;
            hh = __floats2half2_rn(sf[2 * kc][2], sf[2 * kc][3]);         pf[kc][1] = *(uint32_t*)&hh;
            hh = __floats2half2_rn(sf[2 * kc + 1][0], sf[2 * kc + 1][1]); pf[kc][2] = *(uint32_t*)&hh;
            hh = __floats2half2_rn(sf[2 * kc + 1][2], sf[2 * kc + 1][3]); pf[kc][3] = *(uint32_t*)&hh;
        }

#pragma unroll
        for (int kc = 0; kc < 4; kc++) {
#pragma unroll
            for (int nb = 0; nb < 8; nb++) {
                uint32_t t0, t1, t2, t3;
                ldsm_x4_t(t0, t1, t2, t3,
                          smem_u32(Vs + (kc * 16 + a_row) * QSTR + nb * 16 + a_col));
                mma_fp16(of[2 * nb],     pf[kc], t0, t1);
                mma_fp16(of[2 * nb + 1], pf[kc], t2, t3);
            }
        }

        __syncthreads();
        if (jt + 1 < NT) {
            sts_qv();
            __syncthreads();
        }
    }

    // ---- write O as fp16 (input of proj GEMM) ----
    float inv0 = 1.f / l0, inv1 = 1.f / l1;
    int row_g = i0 + w * 16 + (lane >> 2);
    __half* base = O + ((size_t)b * Ll + row_g) * Dd + h * HDh + (lane & 3) * 2;
#pragma unroll
    for (int nf = 0; nf < 16; nf++) {
        __half2 p0 = __floats2half2_rn(of[nf][0] * inv0, of[nf][1] * inv0);
        __half2 p1 = __floats2half2_rn(of[nf][2] * inv1, of[nf][3] * inv1);
        *(__half2*)(base + nf * 8)          = p0;
        *(__half2*)(base + 8 * Dd + nf * 8) = p1;
    }
}

// ---------------------------------------------------------------------------
extern "C" void kernel_launch(void* const* d_in, const int* in_sizes, int n_in,
                              void* d_out, int out_size)
{
    const float* x     = (const float*)d_in[0];
    const float* w_qkv = (const float*)d_in[1];
    const float* b_qkv = (const float*)d_in[2];
    const float* w_out = (const float*)d_in[3];
    const float* b_out = (const float*)d_in[4];
    float* out = (float*)d_out;

    __half *qkvh, *xh, *wqt, *wot, *oh;
    cudaGetSymbolAddress((void**)&qkvh, g_qkvh);
    cudaGetSymbolAddress((void**)&xh,   g_xh);
    cudaGetSymbolAddress((void**)&wqt,  g_wqt);
    cudaGetSymbolAddress((void**)&wot,  g_wot);
    cudaGetSymbolAddress((void**)&oh,   g_oh);

    cudaFuncSetAttribute(gemm_fp16_kernel<true>,
                         cudaFuncAttributeMaxDynamicSharedMemorySize, GEMM_SMEM);
    cudaFuncSetAttribute(gemm_fp16_kernel<false>,
                         cudaFuncAttributeMaxDynamicSharedMemorySize, GEMM_SMEM);
    cudaFuncSetAttribute(attn_mma_kernel,
                         cudaFuncAttributeMaxDynamicSharedMemorySize, ATTN_SMEM);

    // 0) prep: convert x to fp16; transpose+convert weights to K-major fp16
    convert_x_kernel<<<(Mtot * Dd / 4) / 256, 256>>>(x, xh);
    transpose_cvt_kernel<<<dim3(3 * Dd / 32, Dd / 32), 256>>>(w_qkv, wqt, Dd, 3 * Dd);
    transpose_cvt_kernel<<<dim3(Dd / 32, Dd / 32), 256>>>(w_out, wot, Dd, Dd);

    // 1) QKV = X @ W_qkv + b_qkv  -> fp16
    gemm_fp16_kernel<true><<<dim3(3 * Dd / GBN, Mtot / GBM), 256, GEMM_SMEM>>>(
        xh, wqt, b_qkv, qkvh, 3 * Dd, Dd);

    // 2) attention (flash, fp16 mma) -> fp16 O
    attn_mma_kernel<<<dim3(Ll / 128, NHh, Bb), 256, ATTN_SMEM>>>(qkvh, oh);

    // 3) out = O @ W_out + b_out  -> fp32
    gemm_fp16_kernel<false><<<dim3(Dd / GBN, Mtot / GBM), 256, GEMM_SMEM>>>(
        oh, wot, b_out, out, Dd, Dd);
}